// round 14
// baseline (speedup 1.0000x reference)
#include <cuda_runtime.h>
#include <cuda_fp16.h>
#include <math.h>
#include <cstdint>

typedef unsigned long long u64;
typedef unsigned int u32;

#define BB 1024
#define TILES 8
#define NT 512
#define NCTA 128
#define EPSG 1e-5f

// SMEM layout
#define SCR_OFF 0          // 64KB scratch: noise (prologue); stage0@0, stage1@4096 (loop)
#define B0_OFF  65536      // 32KB L0 weight frags
#define B1_OFF  98304      // 64KB L1 weight frags
#define SC_OFF  163840     // 1KB coords
#define SMEM_TOTAL 164864

// ---------------- global scratch ----------------
__device__ u64 g_frag0[16 * 4096];
__device__ u64 g_frag1[16 * 8192];
__device__ float4 g_epi[1024];
__device__ float  g_Wup[128 * 256];
__device__ float  g_hA1[256], g_hW1[256];
__device__ float  g_GAg[4], g_GWg[4], g_BAt[1], g_BWt[1];
// fragment-ordered h buffers, parity double-buffered: [par][tile*16+q][256 uint4]
__device__ uint4  g_h0frag[2][TILES * 16 * 256];
__device__ uint4  g_h1frag[2][TILES * 16 * 256];
__device__ float4 g_part[TILES * 128 * 16];
__device__ float  g_h0f[TILES * 128 * 256];
__device__ uint4  g_flagAv[TILES * 8];   // 16 used words per tile, 128B padded
__device__ uint4  g_flagBv[TILES * 8];
__device__ unsigned g_barc[TILES * 32];

__device__ __forceinline__ float tanh_fast(float x) {
    float y; asm("tanh.approx.f32 %0, %1;" : "=f"(y) : "f"(x)); return y;
}
__device__ __forceinline__ float sig_fast(float x) {
    return 0.5f * tanh_fast(0.5f * x) + 0.5f;
}
__device__ __forceinline__ u32 smem_u32_of(const void* p) {
    u32 a;
    asm("{ .reg .u64 t; cvta.to.shared.u64 t, %1; cvt.u32.u64 %0, t; }" : "=r"(a) : "l"(p));
    return a;
}
#define CP16(dst, src) \
    asm volatile("cp.async.cg.shared.global [%0], [%1], 16;" :: "r"(dst), "l"(src))
#define CP_COMMIT()  asm volatile("cp.async.commit_group;" ::: "memory")
#define CP_WAITALL() asm volatile("cp.async.wait_all;" ::: "memory")

__device__ __forceinline__ void mma16816(float* d, u32 a0, u32 a1, u32 a2, u32 a3,
                                         u32 b0, u32 b1) {
    asm volatile(
        "mma.sync.aligned.m16n8k16.row.col.f32.f16.f16.f32 "
        "{%0,%1,%2,%3}, {%4,%5,%6,%7}, {%8,%9}, {%0,%1,%2,%3};"
        : "+f"(d[0]), "+f"(d[1]), "+f"(d[2]), "+f"(d[3])
        : "r"(a0), "r"(a1), "r"(a2), "r"(a3), "r"(b0), "r"(b1));
}

__device__ __forceinline__ void bar_arrive(int tile) {
    __syncthreads();
    if (threadIdx.x == 0)
        asm volatile("red.release.gpu.global.add.u32 [%0], %1;"
                     :: "l"(&g_barc[tile * 32]), "r"(1u) : "memory");
}
__device__ __forceinline__ void bar_wait(int tile, unsigned target) {
    if (threadIdx.x == 0) {
        unsigned v;
        do {
            asm volatile("ld.acquire.gpu.global.u32 %0, [%1];"
                         : "=r"(v) : "l"(&g_barc[tile * 32]));
        } while (v < target);
    }
    __syncthreads();
}

// all-threads wait: 16 slice flags >= tag (volatile polls + acquire fence)
__device__ __forceinline__ void wait_flags16(const uint4* fv, unsigned tag) {
    for (;;) {
        uint4 a, b, c, d;
        asm volatile("ld.volatile.global.v4.u32 {%0,%1,%2,%3}, [%4];"
                     : "=r"(a.x), "=r"(a.y), "=r"(a.z), "=r"(a.w) : "l"(fv));
        asm volatile("ld.volatile.global.v4.u32 {%0,%1,%2,%3}, [%4];"
                     : "=r"(b.x), "=r"(b.y), "=r"(b.z), "=r"(b.w) : "l"(fv + 1));
        asm volatile("ld.volatile.global.v4.u32 {%0,%1,%2,%3}, [%4];"
                     : "=r"(c.x), "=r"(c.y), "=r"(c.z), "=r"(c.w) : "l"(fv + 2));
        asm volatile("ld.volatile.global.v4.u32 {%0,%1,%2,%3}, [%4];"
                     : "=r"(d.x), "=r"(d.y), "=r"(d.z), "=r"(d.w) : "l"(fv + 3));
        unsigned m = min(min(min(a.x, a.y), min(a.z, a.w)),
                     min(min(min(b.x, b.y), min(b.z, b.w)),
                     min(min(min(c.x, c.y), min(c.z, c.w)),
                         min(min(d.x, d.y), min(d.z, d.w)))));
        if (m >= tag) break;
    }
    asm volatile("fence.acq_rel.gpu;" ::: "memory");
}
__device__ __forceinline__ void flag_release(unsigned* f, unsigned tag) {
    asm volatile("st.release.gpu.global.u32 [%0], %1;" :: "l"(f), "r"(tag) : "memory");
}

__device__ __forceinline__ u64 pack_frag(const float* wr, int k0) {
    __half a = __float2half(wr[k0]),     b = __float2half(wr[k0 + 1]);
    __half c = __float2half(wr[k0 + 8]), d = __float2half(wr[k0 + 9]);
    return (u64)__half_as_ushort(a) | ((u64)__half_as_ushort(b) << 16)
         | ((u64)__half_as_ushort(c) << 32) | ((u64)__half_as_ushort(d) << 48);
}

// ---------------- prep ----------------
__global__ void prep_kernel(const float* __restrict__ W_unpack,
                            const float* __restrict__ Wih0,
                            const float* __restrict__ Whh0,
                            const float* __restrict__ bih0, const float* __restrict__ bhh0,
                            const float* __restrict__ Wih1,
                            const float* __restrict__ Whh1,
                            const float* __restrict__ bih1, const float* __restrict__ bhh1,
                            const float* __restrict__ gamma_a, const float* __restrict__ beta_a,
                            const float* __restrict__ Wa,
                            const float* __restrict__ gamma_w, const float* __restrict__ beta_w,
                            const float* __restrict__ Ww) {
    int i = blockIdx.x * blockDim.x + threadIdx.x;
    if (i < 65536) {
        int q = i >> 12, c = (i >> 8) & 15, ntp = (i >> 6) & 3, lane = (i >> 1) & 31, hs = i & 1;
        int nt = ntp * 2 + hs;
        int nloc = nt * 8 + (lane >> 2);
        int j, gate;
        if (nloc < 32) { j = nloc >> 1; gate = (nloc & 1) ? 1 : 0; }
        else { j = (nloc - 32) >> 1; gate = (nloc & 1) ? 3 : 2; }
        int orig = gate * 256 + q * 16 + j;
        g_frag0[i] = pack_frag(Whh0 + orig * 256, c * 16 + (lane & 3) * 2);
    }
    if (i < 131072) {
        int q = i >> 13, c = (i >> 8) & 31, ntp = (i >> 6) & 3, lane = (i >> 1) & 31, hs = i & 1;
        int nt = ntp * 2 + hs;
        int nloc = nt * 8 + (lane >> 2);
        int j, gate;
        if (nloc < 32) { j = nloc >> 1; gate = (nloc & 1) ? 1 : 0; }
        else { j = (nloc - 32) >> 1; gate = (nloc & 1) ? 3 : 2; }
        int orig = gate * 256 + q * 16 + j;
        const float* src = (c < 16) ? Wih1 : Whh1;
        g_frag1[i] = pack_frag(src + orig * 256, (c & 15) * 16 + (lane & 3) * 2);
    }
    if (i < 1024) {
        int j = i >> 2, comp = i & 3;
        float4 v;
        if (comp == 0)
            v = make_float4(bih0[j] + bhh0[j], bih0[256 + j] + bhh0[256 + j],
                            bih0[512 + j] + bhh0[512 + j], bih0[768 + j] + bhh0[768 + j]);
        else if (comp == 1)
            v = make_float4(Wih0[j * 2], Wih0[(256 + j) * 2],
                            Wih0[(512 + j) * 2], Wih0[(768 + j) * 2]);
        else if (comp == 2)
            v = make_float4(Wih0[j * 2 + 1], Wih0[(256 + j) * 2 + 1],
                            Wih0[(512 + j) * 2 + 1], Wih0[(768 + j) * 2 + 1]);
        else
            v = make_float4(bih1[j] + bhh1[j], bih1[256 + j] + bhh1[256 + j],
                            bih1[512 + j] + bhh1[512 + j], bih1[768 + j] + bhh1[768 + j]);
        g_epi[i] = v;
    }
    if (i < 128 * 256) {
        int k = i >> 8, j = i & 255;
        g_Wup[i] = W_unpack[j * 128 + k];
    }
    if (i < 256) {
        g_hA1[i] = gamma_a[i] * Wa[i];
        g_hW1[i] = gamma_w[i] * Ww[i];
    }
    if (i < 4) {
        float sA = 0.f, sW = 0.f;
        for (int j = i * 64; j < i * 64 + 64; j++) {
            sA += gamma_a[j] * Wa[j];
            sW += gamma_w[j] * Ww[j];
        }
        g_GAg[i] = sA;  g_GWg[i] = sW;
    }
    if (i == 4) {
        float tA = 0.f, tW = 0.f;
        for (int j = 0; j < 256; j++) {
            tA += beta_a[j] * Wa[j];
            tW += beta_w[j] * Ww[j];
        }
        g_BAt[0] = tA;  g_BWt[0] = tW;
    }
    if (i < TILES * 8) {
        g_flagAv[i] = make_uint4(0, 0, 0, 0);
        g_flagBv[i] = make_uint4(0, 0, 0, 0);
    }
    if (i < TILES) g_barc[i * 32] = 0u;
}

// frag-permuted copy: staging (row-major [128][16] halves) -> uint4 frag store
__device__ __forceinline__ void copy_frag_out(u32 stage, uint4* dst, int t) {
    if (t < 256) {
        int m16 = t >> 5, l = t & 31;
        u32 s0 = stage + ((u32)((m16 * 16 + (l >> 2)) * 16 + 2 * (l & 3))) * 2;
        u32 a0, a1, a2, a3;
        asm volatile("ld.shared.b32 %0, [%1];"       : "=r"(a0) : "r"(s0));
        asm volatile("ld.shared.b32 %0, [%1+256];"   : "=r"(a1) : "r"(s0));
        asm volatile("ld.shared.b32 %0, [%1+16];"    : "=r"(a2) : "r"(s0));
        asm volatile("ld.shared.b32 %0, [%1+272];"   : "=r"(a3) : "r"(s0));
        asm volatile("st.global.cg.v4.b32 [%0], {%1,%2,%3,%4};"
                     :: "l"(dst + t), "r"(a0), "r"(a1), "r"(a2), "r"(a3));
    }
}

// ---------------- main ----------------
__global__ __launch_bounds__(NT, 1)
void gen_kernel(const float* __restrict__ noise,
                const float* __restrict__ b_unpack,
                const float* __restrict__ ba, const float* __restrict__ bw,
                int T, float* __restrict__ out) {
    extern __shared__ char smem[];
    const u32 sbase = smem_u32_of(smem);
    const int t = threadIdx.x;
    const int w = t >> 5, lane = t & 31;
    const int wq = w & 7;
    const int wn = w >> 3;
    const int tile = blockIdx.x >> 4;
    const int q = blockIdx.x & 15;
    const int m0 = wq * 16;
    const int r1 = m0 + (lane >> 2);
    const float bav = __ldg(ba), bwv = __ldg(bw);

    const u32 stage0 = sbase + SCR_OFF;
    const u32 stage1 = sbase + SCR_OFF + 4096;
    float2* sc = (float2*)(smem + SC_OFF);
    uint4* h0slice[2] = { &g_h0frag[0][(tile * 16 + q) * 256],
                          &g_h1frag[0][0] };  // placeholder, set below
    h0slice[0] = &g_h0frag[0][(tile * 16 + q) * 256];
    h0slice[1] = &g_h0frag[1][(tile * 16 + q) * 256];
    uint4* h1slice[2] = { &g_h1frag[0][(tile * 16 + q) * 256],
                          &g_h1frag[1][(tile * 16 + q) * 256] };
    unsigned* flagA = ((unsigned*)g_flagAv) + tile * 32 + q;
    unsigned* flagB = ((unsigned*)g_flagBv) + tile * 32 + q;
    const uint4* flagAgrp = g_flagAv + tile * 8;
    const uint4* flagBgrp = g_flagBv + tile * 8;

    const int rp = t >> 2, joff = (t & 3) * 4;
    const float4 pga = *(const float4*)&g_hA1[q * 16 + joff];
    const float4 pgw = *(const float4*)&g_hW1[q * 16 + joff];
    const float gag = g_GAg[(lane & 15) >> 2];
    const float gwg = g_GWg[(lane & 15) >> 2];
    const float BAt = g_BAt[0], BWt = g_BWt[0];

    if (t < 256) ((float*)sc)[t] = 0.f;

    // weights -> SMEM (fragment-ordered)
    for (int u = t; u < 2048; u += NT)
        CP16(sbase + B0_OFF + u * 16, (const char*)(g_frag0 + q * 4096) + u * 16);
    for (int u = t; u < 4096; u += NT)
        CP16(sbase + B1_OFF + u * 16, (const char*)(g_frag1 + q * 8192) + u * 16);
    CP_COMMIT();

    // noise + idea GEMV
    float* nf = (float*)(smem + SCR_OFF);
    for (int i = t; i < 128 * 128; i += NT)
        nf[i] = __ldg(&noise[(size_t)(tile * 128) * 128 + i]);
    __syncthreads();
    float ideav[16];
    if (t < 128) {
#pragma unroll
        for (int j = 0; j < 16; j++) ideav[j] = __ldg(&b_unpack[q * 16 + j]);
        for (int k = 0; k < 128; k++) {
            float nv = nf[t * 128 + k];
            const float* wr = &g_Wup[k * 256 + q * 16];
#pragma unroll
            for (int j = 0; j < 16; j++) ideav[j] = fmaf(nv, __ldg(&wr[j]), ideav[j]);
        }
    }
    __syncthreads();   // nf reads done
    if (t < 128) {
#pragma unroll
        for (int j = 0; j < 16; j++) {
            float v = ideav[j];
            float e = (v > 0.f) ? v : (expf(v) - 1.f);
            asm volatile("st.global.cg.f32 [%0], %1;"
                :: "l"(&g_h0f[(size_t)(tile * 128 + t) * 256 + q * 16 + j]), "f"(e));
            unsigned short hs = __half_as_ushort(__float2half(e));
            asm volatile("st.shared.u16 [%0], %1;" :: "r"(stage0 + (t * 16 + j) * 2), "h"(hs));
        }
    }
    __syncthreads();
    copy_frag_out(stage0, h0slice[1], t);   // idea = "h0new[-1]" -> parity 1
    if (t < 256) {
        // zero h1 buffer parity 1 (read by partA at step 0)
        asm volatile("st.global.cg.v4.b32 [%0], {%1,%1,%1,%1};"
                     :: "l"(h1slice[1] + t), "r"(0u));
    }
    CP_WAITALL();
    bar_arrive(tile);      // E0
    bar_wait(tile, 16);

    // c-state init
    float c0s[2][2], c1s[2][2];
#pragma unroll
    for (int tt = 0; tt < 2; tt++) {
        int jg = q * 16 + 8 * wn + 4 * tt + (lane & 3);
        c0s[0][tt] = g_h0f[(size_t)(tile * 128 + r1) * 256 + jg];
        c0s[1][tt] = g_h0f[(size_t)(tile * 128 + r1 + 8) * 256 + jg];
        c1s[0][tt] = 0.f; c1s[1][tt] = 0.f;
    }

    // per-thread consumer base offsets (chunk stride = 256 uint4)
    const int cbase = tile * 16 * 256 + wq * 32 + lane;

    // ---- prologue hoisted L0 (reads idea frags, parity 1) ----
    float dm0[4][4];
#pragma unroll
    for (int n = 0; n < 4; n++) { dm0[n][0]=dm0[n][1]=dm0[n][2]=dm0[n][3]=0.f; }
    {
        const uint4* rd = &g_h0frag[1][cbase];
        uint4 fa0 = __ldcg(rd), fa1 = __ldcg(rd + 256), fa2 = __ldcg(rd + 512);
#pragma unroll
        for (int c = 0; c < 16; c++) {
            uint4 av = (c % 3 == 0) ? fa0 : (c % 3 == 1) ? fa1 : fa2;
            if (c + 3 < 16) {
                uint4 nx = __ldcg(rd + (c + 3) * 256);
                if (c % 3 == 0) fa0 = nx; else if (c % 3 == 1) fa1 = nx; else fa2 = nx;
            }
#pragma unroll
            for (int pp = 0; pp < 2; pp++) {
                int p = wn + 2 * pp;
                u32 b0, b1, b2, b3;
                asm volatile("ld.shared.v4.b32 {%0,%1,%2,%3}, [%4];"
                             : "=r"(b0), "=r"(b1), "=r"(b2), "=r"(b3)
                             : "r"(sbase + B0_OFF + (c * 4 + p) * 512 + lane * 16));
                mma16816(dm0[pp * 2],     av.x, av.y, av.z, av.w, b0, b1);
                mma16816(dm0[pp * 2 + 1], av.x, av.y, av.z, av.w, b2, b3);
            }
        }
    }
    __syncthreads();

    for (int step = 0; step < T; ++step) {
        const int par = step & 1;
        const unsigned tag = (unsigned)(step + 1);

        // ===== 1. L0 epilogue -> h0new slice (frag order) + flagA =====
        {
            float2 cdA = sc[r1], cdB = sc[r1 + 8];
#pragma unroll
            for (int tt = 0; tt < 2; tt++) {
                int jg = q * 16 + 8 * wn + 4 * tt + (lane & 3);
                int jloc = 8 * wn + 4 * tt + (lane & 3);
                float4 e0 = __ldg(&g_epi[jg * 4 + 0]);
                float4 ea = __ldg(&g_epi[jg * 4 + 1]);
                float4 eb = __ldg(&g_epi[jg * 4 + 2]);
#pragma unroll
                for (int ri = 0; ri < 2; ri++) {
                    float2 cd = ri ? cdB : cdA;
                    float gi = dm0[tt][2*ri]     + e0.x + ea.x * cd.x + eb.x * cd.y;
                    float gf = dm0[tt][2*ri+1]   + e0.y + ea.y * cd.x + eb.y * cd.y;
                    float gg = dm0[2+tt][2*ri]   + e0.z + ea.z * cd.x + eb.z * cd.y;
                    float go = dm0[2+tt][2*ri+1] + e0.w + ea.w * cd.x + eb.w * cd.y;
                    float cn = fmaf(sig_fast(gf), c0s[ri][tt], sig_fast(gi) * tanh_fast(gg));
                    c0s[ri][tt] = cn;
                    unsigned short hs = __half_as_ushort(__float2half(sig_fast(go) * tanh_fast(cn)));
                    asm volatile("st.shared.u16 [%0], %1;"
                                 :: "r"(stage0 + ((r1 + 8 * ri) * 16 + jloc) * 2), "h"(hs));
                }
            }
        }
        __syncthreads();
        copy_frag_out(stage0, h0slice[par], t);
        __syncthreads();
        if (t == 0) flag_release(flagA, tag);

        // ===== 2. L1 partA: h1_prev (parity par^1), B1 chunks 16-31, NO wait ====
        float dm1[4][4];
#pragma unroll
        for (int n = 0; n < 4; n++) { dm1[n][0]=dm1[n][1]=dm1[n][2]=dm1[n][3]=0.f; }
        {
            const uint4* rd = &g_h1frag[par ^ 1][cbase];
            uint4 fa0 = __ldcg(rd), fa1 = __ldcg(rd + 256), fa2 = __ldcg(rd + 512);
#pragma unroll
            for (int c = 0; c < 16; c++) {
                uint4 av = (c % 3 == 0) ? fa0 : (c % 3 == 1) ? fa1 : fa2;
                if (c + 3 < 16) {
                    uint4 nx = __ldcg(rd + (c + 3) * 256);
                    if (c % 3 == 0) fa0 = nx; else if (c % 3 == 1) fa1 = nx; else fa2 = nx;
                }
#pragma unroll
                for (int pp = 0; pp < 2; pp++) {
                    int p = wn + 2 * pp;
                    u32 b0, b1, b2, b3;
                    asm volatile("ld.shared.v4.b32 {%0,%1,%2,%3}, [%4];"
                                 : "=r"(b0), "=r"(b1), "=r"(b2), "=r"(b3)
                                 : "r"(sbase + B1_OFF + ((c + 16) * 4 + p) * 512 + lane * 16));
                    mma16816(dm1[pp * 2],     av.x, av.y, av.z, av.w, b0, b1);
                    mma16816(dm1[pp * 2 + 1], av.x, av.y, av.z, av.w, b2, b3);
                }
            }
        }

        // ===== 3. wait flagA; partB: h0new (parity par), B1 chunks 0-15 =====
        wait_flags16(flagAgrp, tag);
        {
            const uint4* rd = &g_h0frag[par][cbase];
            uint4 fa0 = __ldcg(rd), fa1 = __ldcg(rd + 256), fa2 = __ldcg(rd + 512);
#pragma unroll
            for (int c = 0; c < 16; c++) {
                uint4 av = (c % 3 == 0) ? fa0 : (c % 3 == 1) ? fa1 : fa2;
                if (c + 3 < 16) {
                    uint4 nx = __ldcg(rd + (c + 3) * 256);
                    if (c % 3 == 0) fa0 = nx; else if (c % 3 == 1) fa1 = nx; else fa2 = nx;
                }
#pragma unroll
                for (int pp = 0; pp < 2; pp++) {
                    int p = wn + 2 * pp;
                    u32 b0, b1, b2, b3;
                    asm volatile("ld.shared.v4.b32 {%0,%1,%2,%3}, [%4];"
                                 : "=r"(b0), "=r"(b1), "=r"(b2), "=r"(b3)
                                 : "r"(sbase + B1_OFF + (c * 4 + p) * 512 + lane * 16));
                    mma16816(dm1[pp * 2],     av.x, av.y, av.z, av.w, b0, b1);
                    mma16816(dm1[pp * 2 + 1], av.x, av.y, av.z, av.w, b2, b3);
                }
            }
        }

        // ===== 4. L1 epilogue -> stage1; frag copy + GN partials; flagB =====
#pragma unroll
        for (int tt = 0; tt < 2; tt++) {
            int jg = q * 16 + 8 * wn + 4 * tt + (lane & 3);
            int jloc = 8 * wn + 4 * tt + (lane & 3);
            float4 e3 = __ldg(&g_epi[jg * 4 + 3]);
#pragma unroll
            for (int ri = 0; ri < 2; ri++) {
                float gi = dm1[tt][2*ri]     + e3.x;
                float gf = dm1[tt][2*ri+1]   + e3.y;
                float gg = dm1[2+tt][2*ri]   + e3.z;
                float go = dm1[2+tt][2*ri+1] + e3.w;
                float cn = fmaf(sig_fast(gf), c1s[ri][tt], sig_fast(gi) * tanh_fast(gg));
                c1s[ri][tt] = cn;
                unsigned short hs = __half_as_ushort(__float2half(sig_fast(go) * tanh_fast(cn)));
                asm volatile("st.shared.u16 [%0], %1;"
                             :: "r"(stage1 + ((r1 + 8 * ri) * 16 + jloc) * 2), "h"(hs));
            }
        }
        __syncthreads();
        copy_frag_out(stage1, h1slice[par], t);
        {
            u64 hv;
            asm volatile("ld.shared.b64 %0, [%1];"
                         : "=l"(hv) : "r"(stage1 + (rp * 16 + joff) * 2));
            float2 fA = __half22float2(*(__half2*)&hv);
            float2 fB = __half22float2(*((__half2*)&hv + 1));
            float f0 = fA.x, f1 = fA.y, f2 = fB.x, f3 = fB.y;
            float sh  = f0 + f1 + f2 + f3;
            float sh2 = fmaf(f0, f0, fmaf(f1, f1, fmaf(f2, f2, f3 * f3)));
            float sA  = f0 * pga.x + f1 * pga.y + f2 * pga.z + f3 * pga.w;
            float sW  = f0 * pgw.x + f1 * pgw.y + f2 * pgw.z + f3 * pgw.w;
#pragma unroll
            for (int off = 1; off < 4; off <<= 1) {
                sh  += __shfl_xor_sync(0xffffffffu, sh,  off);
                sh2 += __shfl_xor_sync(0xffffffffu, sh2, off);
                sA  += __shfl_xor_sync(0xffffffffu, sA,  off);
                sW  += __shfl_xor_sync(0xffffffffu, sW,  off);
            }
            if ((t & 3) == 0) {
                float4* pp4 = &g_part[(size_t)(tile * 128 + rp) * 16 + q];
                asm volatile("st.global.cg.v4.f32 [%0], {%1,%2,%3,%4};"
                             :: "l"(pp4), "f"(sh), "f"(sh2), "f"(sA), "f"(sW));
            }
        }
        __syncthreads();
        if (t == 0) flag_release(flagB, tag);

        // ===== 5. hoisted L0 MMA for step+1 (h0new parity par, flagA acquired) ====
#pragma unroll
        for (int n = 0; n < 4; n++) { dm0[n][0]=dm0[n][1]=dm0[n][2]=dm0[n][3]=0.f; }
        {
            const uint4* rd = &g_h0frag[par][cbase];
            uint4 fa0 = __ldcg(rd), fa1 = __ldcg(rd + 256), fa2 = __ldcg(rd + 512);
#pragma unroll
            for (int c = 0; c < 16; c++) {
                uint4 av = (c % 3 == 0) ? fa0 : (c % 3 == 1) ? fa1 : fa2;
                if (c + 3 < 16) {
                    uint4 nx = __ldcg(rd + (c + 3) * 256);
                    if (c % 3 == 0) fa0 = nx; else if (c % 3 == 1) fa1 = nx; else fa2 = nx;
                }
#pragma unroll
                for (int pp = 0; pp < 2; pp++) {
                    int p = wn + 2 * pp;
                    u32 b0, b1, b2, b3;
                    asm volatile("ld.shared.v4.b32 {%0,%1,%2,%3}, [%4];"
                                 : "=r"(b0), "=r"(b1), "=r"(b2), "=r"(b3)
                                 : "r"(sbase + B0_OFF + (c * 4 + p) * 512 + lane * 16));
                    mma16816(dm0[pp * 2],     av.x, av.y, av.z, av.w, b0, b1);
                    mma16816(dm0[pp * 2 + 1], av.x, av.y, av.z, av.w, b2, b3);
                }
            }
        }

        // ===== 6. wait flagB; combine partials -> coords =====
        wait_flags16(flagBgrp, tag);
#pragma unroll
        for (int ps = 0; ps < 4; ps++) {
            int row = w * 8 + 2 * ps + (lane >> 4);
            int qp = lane & 15;
            float4 P = __ldcg(&g_part[(size_t)(tile * 128 + row) * 16 + qp]);
            float sh = P.x, sh2 = P.y, sA = P.z, sW = P.w;
#pragma unroll
            for (int off = 1; off < 4; off <<= 1) {
                sh  += __shfl_xor_sync(0xffffffffu, sh,  off);
                sh2 += __shfl_xor_sync(0xffffffffu, sh2, off);
                sA  += __shfl_xor_sync(0xffffffffu, sA,  off);
                sW  += __shfl_xor_sync(0xffffffffu, sW,  off);
            }
            float mu   = sh * (1.f / 64.f);
            float var  = sh2 * (1.f / 64.f) - mu * mu;
            float rstd = rsqrtf(var + EPSG);
            float vA = rstd * (sA - mu * gag);
            float vW = rstd * (sW - mu * gwg);
            if (lane & 3) { vA = 0.f; vW = 0.f; }
#pragma unroll
            for (int off = 4; off < 16; off <<= 1) {
                vA += __shfl_xor_sync(0xffffffffu, vA, off);
                vW += __shfl_xor_sync(0xffffffffu, vW, off);
            }
            if ((lane & 15) == 0) {
                float ang = tanh_fast(vA + BAt + bav);
                float wdt = sig_fast(vW + BWt + bwv);
                sc[row] = make_float2(ang, wdt);
                if (q == (row >> 3)) {
                    float2* op = (float2*)(out + ((size_t)(tile * 128 + row) * T + step) * 2);
                    *op = make_float2(ang, wdt);
                }
            }
        }
        __syncthreads();
    }
}

extern "C" void kernel_launch(void* const* d_in, const int* in_sizes, int n_in,
                              void* d_out, int out_size) {
    const float* noise    = (const float*)d_in[0];
    const float* W_unpack = (const float*)d_in[1];
    const float* b_unpack = (const float*)d_in[2];
    const float* Wih0     = (const float*)d_in[3];
    const float* Whh0     = (const float*)d_in[4];
    const float* bih0     = (const float*)d_in[5];
    const float* bhh0     = (const float*)d_in[6];
    const float* Wih1     = (const float*)d_in[7];
    const float* Whh1     = (const float*)d_in[8];
    const float* bih1     = (const float*)d_in[9];
    const float* bhh1     = (const float*)d_in[10];
    const float* gamma_a  = (const float*)d_in[11];
    const float* beta_a   = (const float*)d_in[12];
    const float* Wa       = (const float*)d_in[13];
    const float* ba       = (const float*)d_in[14];
    const float* gamma_w  = (const float*)d_in[15];
    const float* beta_w   = (const float*)d_in[16];
    const float* Ww       = (const float*)d_in[17];
    const float* bw       = (const float*)d_in[18];
    (void)in_sizes; (void)n_in;

    int T = out_size / (BB * 2);

    cudaFuncSetAttribute(gen_kernel, cudaFuncAttributeMaxDynamicSharedMemorySize, SMEM_TOTAL);
    prep_kernel<<<512, 256>>>(W_unpack, Wih0, Whh0, bih0, bhh0, Wih1, Whh1, bih1, bhh1,
                              gamma_a, beta_a, Wa, gamma_w, beta_w, Ww);
    gen_kernel<<<NCTA, NT, SMEM_TOTAL>>>(noise, b_unpack, ba, bw, T, (float*)d_out);
}

// round 15
// speedup vs baseline: 1.0922x; 1.0922x over previous
#include <cuda_runtime.h>
#include <cuda_fp16.h>
#include <math.h>
#include <cstdint>

typedef unsigned long long u64;
typedef unsigned int u32;

#define BB 1024
#define TILES 8
#define NT 512
#define NCTA 128
#define EPSG 1e-5f

#define A_OFF  0          // 32 k-chunks * 4096B (0-15: h0, 16-31: h1); chunk0/16 double as staging
#define B0_OFF 131072
#define B1_OFF 163840
#define SC_OFF 229376     // 128 float2 coords
#define SMEM_TOTAL 230400

// ---------------- global scratch ----------------
__device__ u64 g_frag0[16 * 4096];
__device__ u64 g_frag1[16 * 8192];
__device__ float4 g_epi[1024];
__device__ float  g_Wup[128 * 256];
__device__ float  g_hA1[256], g_hW1[256];
__device__ float  g_GAg[4], g_GWg[4], g_BAt[1], g_BWt[1];
__device__ __half g_h0p[TILES * 16 * 128 * 16];   // [tile][q][row][16]
__device__ __half g_h1p[TILES * 16 * 128 * 16];
__device__ float4 g_part[TILES * 128 * 16];       // [tile][row][q] GN partials
__device__ float  g_h0f[TILES * 128 * 256];
__device__ unsigned g_barc[TILES * 32];

__device__ __forceinline__ float tanh_fast(float x) {
    float y; asm("tanh.approx.f32 %0, %1;" : "=f"(y) : "f"(x)); return y;
}
__device__ __forceinline__ float sig_fast(float x) {
    return 0.5f * tanh_fast(0.5f * x) + 0.5f;
}
__device__ __forceinline__ u32 smem_u32_of(const void* p) {
    u32 a;
    asm("{ .reg .u64 t; cvta.to.shared.u64 t, %1; cvt.u32.u64 %0, t; }" : "=r"(a) : "l"(p));
    return a;
}
#define CP16(dst, src) \
    asm volatile("cp.async.cg.shared.global [%0], [%1], 16;" :: "r"(dst), "l"(src))
#define CP_COMMIT()  asm volatile("cp.async.commit_group;" ::: "memory")
#define CP_WAITALL() asm volatile("cp.async.wait_all;" ::: "memory")
#define CP_WAITGRP(n) asm volatile("cp.async.wait_group %0;" :: "n"(n) : "memory")

__device__ __forceinline__ void mma16816(float* d, u32 a0, u32 a1, u32 a2, u32 a3,
                                         u32 b0, u32 b1) {
    asm volatile(
        "mma.sync.aligned.m16n8k16.row.col.f32.f16.f16.f32 "
        "{%0,%1,%2,%3}, {%4,%5,%6,%7}, {%8,%9}, {%0,%1,%2,%3};"
        : "+f"(d[0]), "+f"(d[1]), "+f"(d[2]), "+f"(d[3])
        : "r"(a0), "r"(a1), "r"(a2), "r"(a3), "r"(b0), "r"(b1));
}

__device__ __forceinline__ void bar_arrive(int tile) {
    __syncthreads();
    if (threadIdx.x == 0)
        asm volatile("red.release.gpu.global.add.u32 [%0], %1;"
                     :: "l"(&g_barc[tile * 32]), "r"(1u) : "memory");
}
__device__ __forceinline__ void bar_wait(int tile, unsigned target) {
    if (threadIdx.x == 0) {
        unsigned v;
        do {
            asm volatile("ld.acquire.gpu.global.u32 %0, [%1];"
                         : "=r"(v) : "l"(&g_barc[tile * 32]));
        } while (v < target);
    }
    __syncthreads();
}

__device__ __forceinline__ u64 pack_frag(const float* wr, int k0) {
    __half a = __float2half(wr[k0]),     b = __float2half(wr[k0 + 1]);
    __half c = __float2half(wr[k0 + 8]), d = __float2half(wr[k0 + 9]);
    return (u64)__half_as_ushort(a) | ((u64)__half_as_ushort(b) << 16)
         | ((u64)__half_as_ushort(c) << 32) | ((u64)__half_as_ushort(d) << 48);
}

// ---------------- prep ----------------
__global__ void prep_kernel(const float* __restrict__ W_unpack,
                            const float* __restrict__ Wih0,
                            const float* __restrict__ Whh0,
                            const float* __restrict__ bih0, const float* __restrict__ bhh0,
                            const float* __restrict__ Wih1,
                            const float* __restrict__ Whh1,
                            const float* __restrict__ bih1, const float* __restrict__ bhh1,
                            const float* __restrict__ gamma_a, const float* __restrict__ beta_a,
                            const float* __restrict__ Wa,
                            const float* __restrict__ gamma_w, const float* __restrict__ beta_w,
                            const float* __restrict__ Ww) {
    int i = blockIdx.x * blockDim.x + threadIdx.x;
    if (i < 65536) {
        int q = i >> 12, c = (i >> 8) & 15, ntp = (i >> 6) & 3, lane = (i >> 1) & 31, hs = i & 1;
        int nt = ntp * 2 + hs;
        int nloc = nt * 8 + (lane >> 2);
        int j, gate;
        if (nloc < 32) { j = nloc >> 1; gate = (nloc & 1) ? 1 : 0; }
        else { j = (nloc - 32) >> 1; gate = (nloc & 1) ? 3 : 2; }
        int orig = gate * 256 + q * 16 + j;
        g_frag0[i] = pack_frag(Whh0 + orig * 256, c * 16 + (lane & 3) * 2);
    }
    if (i < 131072) {
        int q = i >> 13, c = (i >> 8) & 31, ntp = (i >> 6) & 3, lane = (i >> 1) & 31, hs = i & 1;
        int nt = ntp * 2 + hs;
        int nloc = nt * 8 + (lane >> 2);
        int j, gate;
        if (nloc < 32) { j = nloc >> 1; gate = (nloc & 1) ? 1 : 0; }
        else { j = (nloc - 32) >> 1; gate = (nloc & 1) ? 3 : 2; }
        int orig = gate * 256 + q * 16 + j;
        const float* src = (c < 16) ? Wih1 : Whh1;
        g_frag1[i] = pack_frag(src + orig * 256, (c & 15) * 16 + (lane & 3) * 2);
    }
    if (i < 1024) {
        int j = i >> 2, comp = i & 3;
        float4 v;
        if (comp == 0)
            v = make_float4(bih0[j] + bhh0[j], bih0[256 + j] + bhh0[256 + j],
                            bih0[512 + j] + bhh0[512 + j], bih0[768 + j] + bhh0[768 + j]);
        else if (comp == 1)
            v = make_float4(Wih0[j * 2], Wih0[(256 + j) * 2],
                            Wih0[(512 + j) * 2], Wih0[(768 + j) * 2]);
        else if (comp == 2)
            v = make_float4(Wih0[j * 2 + 1], Wih0[(256 + j) * 2 + 1],
                            Wih0[(512 + j) * 2 + 1], Wih0[(768 + j) * 2 + 1]);
        else
            v = make_float4(bih1[j] + bhh1[j], bih1[256 + j] + bhh1[256 + j],
                            bih1[512 + j] + bhh1[512 + j], bih1[768 + j] + bhh1[768 + j]);
        g_epi[i] = v;
    }
    if (i < 128 * 256) {
        int k = i >> 8, j = i & 255;
        g_Wup[i] = W_unpack[j * 128 + k];
    }
    if (i < 256) {
        g_hA1[i] = gamma_a[i] * Wa[i];
        g_hW1[i] = gamma_w[i] * Ww[i];
    }
    if (i < 4) {
        float sA = 0.f, sW = 0.f;
        for (int j = i * 64; j < i * 64 + 64; j++) {
            sA += gamma_a[j] * Wa[j];
            sW += gamma_w[j] * Ww[j];
        }
        g_GAg[i] = sA;  g_GWg[i] = sW;
    }
    if (i == 4) {
        float tA = 0.f, tW = 0.f;
        for (int j = 0; j < 256; j++) {
            tA += beta_a[j] * Wa[j];
            tW += beta_w[j] * Ww[j];
        }
        g_BAt[0] = tA;  g_BWt[0] = tW;
    }
    if (i < TILES) g_barc[i * 32] = 0u;
}

// ---------------- main ----------------
__global__ __launch_bounds__(NT, 1)
void gen_kernel(const float* __restrict__ noise,
                const float* __restrict__ b_unpack,
                const float* __restrict__ ba, const float* __restrict__ bw,
                int T, float* __restrict__ out) {
    extern __shared__ char smem[];
    const u32 sbase = smem_u32_of(smem);
    const int t = threadIdx.x;
    const int w = t >> 5, lane = t & 31;
    const int wq = w & 7;
    const int wn = w >> 3;
    const int tile = blockIdx.x >> 4;
    const int q = blockIdx.x & 15;
    const int m0 = wq * 16;
    const int r1 = m0 + (lane >> 2);
    const float bav = __ldg(ba), bwv = __ldg(bw);

    const u32 stage0 = sbase + A_OFF;
    const u32 stage1 = sbase + A_OFF + 65536;
    float2* sc = (float2*)(smem + SC_OFF);
    __half* h0slice = (__half*)&g_h0p[(size_t)(tile * 16 + q) * 2048];
    __half* h1slice = (__half*)&g_h1p[(size_t)(tile * 16 + q) * 2048];

    const int rp = t >> 2, joff = (t & 3) * 4;
    const float4 pga = *(const float4*)&g_hA1[q * 16 + joff];
    const float4 pgw = *(const float4*)&g_hW1[q * 16 + joff];
    const float gag = g_GAg[(lane & 15) >> 2];
    const float gwg = g_GWg[(lane & 15) >> 2];
    const float BAt = g_BAt[0], BWt = g_BWt[0];

    if (t < 256) ((float*)sc)[t] = 0.f;

    // weights -> SMEM (fragment-ordered)
    for (int u = t; u < 2048; u += NT)
        CP16(sbase + B0_OFF + u * 16, (const char*)(g_frag0 + q * 4096) + u * 16);
    for (int u = t; u < 4096; u += NT)
        CP16(sbase + B1_OFF + u * 16, (const char*)(g_frag1 + q * 8192) + u * 16);
    CP_COMMIT();

    // noise + idea GEMV
    float* nf = (float*)(smem + A_OFF);
    for (int i = t; i < 128 * 128; i += NT)
        nf[i] = __ldg(&noise[(size_t)(tile * 128) * 128 + i]);
    __syncthreads();
    float ideav[16];
    if (t < 128) {
#pragma unroll
        for (int j = 0; j < 16; j++) ideav[j] = __ldg(&b_unpack[q * 16 + j]);
        for (int k = 0; k < 128; k++) {
            float nv = nf[t * 128 + k];
            const float* wr = &g_Wup[k * 256 + q * 16];
#pragma unroll
            for (int j = 0; j < 16; j++) ideav[j] = fmaf(nv, __ldg(&wr[j]), ideav[j]);
        }
    }
    __syncthreads();
    if (t < 128) {
#pragma unroll
        for (int j = 0; j < 16; j++) {
            float v = ideav[j];
            float e = (v > 0.f) ? v : (expf(v) - 1.f);
            asm volatile("st.global.cg.f32 [%0], %1;"
                :: "l"(&g_h0f[(size_t)(tile * 128 + t) * 256 + q * 16 + j]), "f"(e));
            unsigned short hs = __half_as_ushort(__float2half(e));
            asm volatile("st.shared.u16 [%0], %1;" :: "r"(stage0 + (t * 16 + j) * 2), "h"(hs));
        }
    }
    __syncthreads();
    if (t < 256) {
        u32 v0, v1, v2, v3;
        asm volatile("ld.shared.v4.b32 {%0,%1,%2,%3}, [%4];"
                     : "=r"(v0), "=r"(v1), "=r"(v2), "=r"(v3) : "r"(stage0 + t * 16));
        asm volatile("st.global.cg.v4.b32 [%0], {%1,%2,%3,%4};"
                     :: "l"((char*)h0slice + t * 16), "r"(v0), "r"(v1), "r"(v2), "r"(v3));
    }
    CP_WAITALL();          // weights landed
    bar_arrive(tile);      // E0: idea h0 published
    unsigned bt = 16;
    bar_wait(tile, bt);

    // c-state init
    float c0s[2][2], c1s[2][2];
#pragma unroll
    for (int tt = 0; tt < 2; tt++) {
        int jg = q * 16 + 8 * wn + 4 * tt + (lane & 3);
        c0s[0][tt] = g_h0f[(size_t)(tile * 128 + r1) * 256 + jg];
        c0s[1][tt] = g_h0f[(size_t)(tile * 128 + r1 + 8) * 256 + jg];
        c1s[0][tt] = 0.f; c1s[1][tt] = 0.f;
    }

    // A chunks 0-15 <- h0 (packed), 16-31 <- 0
    for (int u = t; u < 4096; u += NT) {
        int c = u >> 8, rem = u & 255, m = rem >> 1, hi = rem & 1;
        u32 dst = sbase + A_OFF + c * 4096 + m * 32 + (((hi ^ (m >> 2)) & 1) << 4);
        CP16(dst, &g_h0p[(size_t)((tile * 16 + c) * 128 + m) * 16 + hi * 8]);
    }
    CP_COMMIT();
    {
        uint4 z = make_uint4(0, 0, 0, 0);
        uint4* az = (uint4*)(smem + A_OFF + 65536);
        for (int i = t; i < 4096; i += NT) az[i] = z;
    }
    CP_WAITALL();
    __syncthreads();

    const u32 aBase = sbase + A_OFF + (m0 + (lane & 15)) * 32 +
                      (((lane >> 4) ^ (((lane & 15) >> 2) & 1)) << 4);

    // ---- prologue: hoisted L0 MMA for step 0 ----
    float dm0[4][4];
#pragma unroll
    for (int n = 0; n < 4; n++) { dm0[n][0]=dm0[n][1]=dm0[n][2]=dm0[n][3]=0.f; }
#pragma unroll
    for (int c = 0; c < 16; c++) {
        u32 a0, a1, a2, a3;
        asm volatile("ldmatrix.sync.aligned.m8n8.x4.shared.b16 {%0,%1,%2,%3}, [%4];"
                     : "=r"(a0), "=r"(a1), "=r"(a2), "=r"(a3) : "r"(aBase + c * 4096));
#pragma unroll
        for (int pp = 0; pp < 2; pp++) {
            int p = wn + 2 * pp;
            u32 b0, b1, b2, b3;
            asm volatile("ld.shared.v4.b32 {%0,%1,%2,%3}, [%4];"
                         : "=r"(b0), "=r"(b1), "=r"(b2), "=r"(b3)
                         : "r"(sbase + B0_OFF + (c * 4 + p) * 512 + lane * 16));
            mma16816(dm0[pp * 2],     a0, a1, a2, a3, b0, b1);
            mma16816(dm0[pp * 2 + 1], a0, a1, a2, a3, b2, b3);
        }
    }
    __syncthreads();   // L0 reads done before epilogue stages into chunk0

    for (int step = 0; step < T; ++step) {
        // ===== 1. L0 epilogue (dm0 + local coords) -> h0new slice =====
        {
            float2 cdA = sc[r1], cdB = sc[r1 + 8];
#pragma unroll
            for (int tt = 0; tt < 2; tt++) {
                int jg = q * 16 + 8 * wn + 4 * tt + (lane & 3);
                int jloc = 8 * wn + 4 * tt + (lane & 3);
                float4 e0 = __ldg(&g_epi[jg * 4 + 0]);
                float4 ea = __ldg(&g_epi[jg * 4 + 1]);
                float4 eb = __ldg(&g_epi[jg * 4 + 2]);
#pragma unroll
                for (int ri = 0; ri < 2; ri++) {
                    float2 cd = ri ? cdB : cdA;
                    float gi = dm0[tt][2*ri]     + e0.x + ea.x * cd.x + eb.x * cd.y;
                    float gf = dm0[tt][2*ri+1]   + e0.y + ea.y * cd.x + eb.y * cd.y;
                    float gg = dm0[2+tt][2*ri]   + e0.z + ea.z * cd.x + eb.z * cd.y;
                    float go = dm0[2+tt][2*ri+1] + e0.w + ea.w * cd.x + eb.w * cd.y;
                    float cn = fmaf(sig_fast(gf), c0s[ri][tt], sig_fast(gi) * tanh_fast(gg));
                    c0s[ri][tt] = cn;
                    unsigned short hs = __half_as_ushort(__float2half(sig_fast(go) * tanh_fast(cn)));
                    asm volatile("st.shared.u16 [%0], %1;"
                                 :: "r"(stage0 + ((r1 + 8 * ri) * 16 + jloc) * 2), "h"(hs));
                }
            }
        }
        __syncthreads();
        if (t < 256) {
            u32 v0, v1, v2, v3;
            asm volatile("ld.shared.v4.b32 {%0,%1,%2,%3}, [%4];"
                         : "=r"(v0), "=r"(v1), "=r"(v2), "=r"(v3) : "r"(stage0 + t * 16));
            asm volatile("st.global.cg.v4.b32 [%0], {%1,%2,%3,%4};"
                         :: "l"((char*)h0slice + t * 16), "r"(v0), "r"(v1), "r"(v2), "r"(v3));
        }
        bar_arrive(tile);   // event A: h0new published

        // ===== 2. L1 partA: chunks 16-31 (h1_prev) =====
        float dm1[4][4];
#pragma unroll
        for (int n = 0; n < 4; n++) { dm1[n][0]=dm1[n][1]=dm1[n][2]=dm1[n][3]=0.f; }
#pragma unroll
        for (int c = 16; c < 32; c++) {
            u32 a0, a1, a2, a3;
            asm volatile("ldmatrix.sync.aligned.m8n8.x4.shared.b16 {%0,%1,%2,%3}, [%4];"
                         : "=r"(a0), "=r"(a1), "=r"(a2), "=r"(a3) : "r"(aBase + c * 4096));
#pragma unroll
            for (int pp = 0; pp < 2; pp++) {
                int p = wn + 2 * pp;
                u32 b0, b1, b2, b3;
                asm volatile("ld.shared.v4.b32 {%0,%1,%2,%3}, [%4];"
                             : "=r"(b0), "=r"(b1), "=r"(b2), "=r"(b3)
                             : "r"(sbase + B1_OFF + (c * 4 + p) * 512 + lane * 16));
                mma16816(dm1[pp * 2],     a0, a1, a2, a3, b0, b1);
                mma16816(dm1[pp * 2 + 1], a0, a1, a2, a3, b2, b3);
            }
        }
        // ===== 3. wait A; PIPELINED reload h0new (2 groups) + partB =====
        bt += 16; bar_wait(tile, bt);
        for (int u = t; u < 2048; u += NT) {              // group 1: chunks 0-7
            int c = u >> 8, rem = u & 255, m = rem >> 1, hi = rem & 1;
            u32 dst = sbase + A_OFF + c * 4096 + m * 32 + (((hi ^ (m >> 2)) & 1) << 4);
            CP16(dst, &g_h0p[(size_t)((tile * 16 + c) * 128 + m) * 16 + hi * 8]);
        }
        CP_COMMIT();
        for (int u = t + 2048; u < 4096; u += NT) {       // group 2: chunks 8-15
            int c = u >> 8, rem = u & 255, m = rem >> 1, hi = rem & 1;
            u32 dst = sbase + A_OFF + c * 4096 + m * 32 + (((hi ^ (m >> 2)) & 1) << 4);
            CP16(dst, &g_h0p[(size_t)((tile * 16 + c) * 128 + m) * 16 + hi * 8]);
        }
        CP_COMMIT();
        CP_WAITGRP(1);          // chunks 0-7 resident
        __syncthreads();
        // ===== 4a. L1 partB chunks 0-7 =====
#pragma unroll
        for (int c = 0; c < 8; c++) {
            u32 a0, a1, a2, a3;
            asm volatile("ldmatrix.sync.aligned.m8n8.x4.shared.b16 {%0,%1,%2,%3}, [%4];"
                         : "=r"(a0), "=r"(a1), "=r"(a2), "=r"(a3) : "r"(aBase + c * 4096));
#pragma unroll
            for (int pp = 0; pp < 2; pp++) {
                int p = wn + 2 * pp;
                u32 b0, b1, b2, b3;
                asm volatile("ld.shared.v4.b32 {%0,%1,%2,%3}, [%4];"
                             : "=r"(b0), "=r"(b1), "=r"(b2), "=r"(b3)
                             : "r"(sbase + B1_OFF + (c * 4 + p) * 512 + lane * 16));
                mma16816(dm1[pp * 2],     a0, a1, a2, a3, b0, b1);
                mma16816(dm1[pp * 2 + 1], a0, a1, a2, a3, b2, b3);
            }
        }
        CP_WAITGRP(0);          // chunks 8-15 resident
        __syncthreads();
        // ===== 4b. L1 partB chunks 8-15 =====
#pragma unroll
        for (int c = 8; c < 16; c++) {
            u32 a0, a1, a2, a3;
            asm volatile("ldmatrix.sync.aligned.m8n8.x4.shared.b16 {%0,%1,%2,%3}, [%4];"
                         : "=r"(a0), "=r"(a1), "=r"(a2), "=r"(a3) : "r"(aBase + c * 4096));
#pragma unroll
            for (int pp = 0; pp < 2; pp++) {
                int p = wn + 2 * pp;
                u32 b0, b1, b2, b3;
                asm volatile("ld.shared.v4.b32 {%0,%1,%2,%3}, [%4];"
                             : "=r"(b0), "=r"(b1), "=r"(b2), "=r"(b3)
                             : "r"(sbase + B1_OFF + (c * 4 + p) * 512 + lane * 16));
                mma16816(dm1[pp * 2],     a0, a1, a2, a3, b0, b1);
                mma16816(dm1[pp * 2 + 1], a0, a1, a2, a3, b2, b3);
            }
        }
        // ===== 4c. L1 epilogue + GN partials =====
#pragma unroll
        for (int tt = 0; tt < 2; tt++) {
            int jg = q * 16 + 8 * wn + 4 * tt + (lane & 3);
            int jloc = 8 * wn + 4 * tt + (lane & 3);
            float4 e3 = __ldg(&g_epi[jg * 4 + 3]);
#pragma unroll
            for (int ri = 0; ri < 2; ri++) {
                float gi = dm1[tt][2*ri]     + e3.x;
                float gf = dm1[tt][2*ri+1]   + e3.y;
                float gg = dm1[2+tt][2*ri]   + e3.z;
                float go = dm1[2+tt][2*ri+1] + e3.w;
                float cn = fmaf(sig_fast(gf), c1s[ri][tt], sig_fast(gi) * tanh_fast(gg));
                c1s[ri][tt] = cn;
                unsigned short hs = __half_as_ushort(__float2half(sig_fast(go) * tanh_fast(cn)));
                asm volatile("st.shared.u16 [%0], %1;"
                             :: "r"(stage1 + ((r1 + 8 * ri) * 16 + jloc) * 2), "h"(hs));
            }
        }
        __syncthreads();
        if (t < 256) {
            u32 v0, v1, v2, v3;
            asm volatile("ld.shared.v4.b32 {%0,%1,%2,%3}, [%4];"
                         : "=r"(v0), "=r"(v1), "=r"(v2), "=r"(v3) : "r"(stage1 + t * 16));
            asm volatile("st.global.cg.v4.b32 [%0], {%1,%2,%3,%4};"
                         :: "l"((char*)h1slice + t * 16), "r"(v0), "r"(v1), "r"(v2), "r"(v3));
        }
        {
            u64 hv;
            asm volatile("ld.shared.b64 %0, [%1];"
                         : "=l"(hv) : "r"(stage1 + (rp * 16 + joff) * 2));
            float2 fa = __half22float2(*(__half2*)&hv);
            float2 fb = __half22float2(*((__half2*)&hv + 1));
            float f0 = fa.x, f1 = fa.y, f2 = fb.x, f3 = fb.y;
            float sh  = f0 + f1 + f2 + f3;
            float sh2 = fmaf(f0, f0, fmaf(f1, f1, fmaf(f2, f2, f3 * f3)));
            float sA  = f0 * pga.x + f1 * pga.y + f2 * pga.z + f3 * pga.w;
            float sW  = f0 * pgw.x + f1 * pgw.y + f2 * pgw.z + f3 * pgw.w;
#pragma unroll
            for (int off = 1; off < 4; off <<= 1) {
                sh  += __shfl_xor_sync(0xffffffffu, sh,  off);
                sh2 += __shfl_xor_sync(0xffffffffu, sh2, off);
                sA  += __shfl_xor_sync(0xffffffffu, sA,  off);
                sW  += __shfl_xor_sync(0xffffffffu, sW,  off);
            }
            if ((t & 3) == 0) {
                float4* pp4 = &g_part[(size_t)(tile * 128 + rp) * 16 + q];
                asm volatile("st.global.cg.v4.f32 [%0], {%1,%2,%3,%4};"
                             :: "l"(pp4), "f"(sh), "f"(sh2), "f"(sA), "f"(sW));
            }
        }
        bar_arrive(tile);   // event B: h1new + partials published

        // ===== 5. hoisted L0 MMA for step+1 (chunks 0-15 = h0new) =====
#pragma unroll
        for (int n = 0; n < 4; n++) { dm0[n][0]=dm0[n][1]=dm0[n][2]=dm0[n][3]=0.f; }
#pragma unroll
        for (int c = 0; c < 16; c++) {
            u32 a0, a1, a2, a3;
            asm volatile("ldmatrix.sync.aligned.m8n8.x4.shared.b16 {%0,%1,%2,%3}, [%4];"
                         : "=r"(a0), "=r"(a1), "=r"(a2), "=r"(a3) : "r"(aBase + c * 4096));
#pragma unroll
            for (int pp = 0; pp < 2; pp++) {
                int p = wn + 2 * pp;
                u32 b0, b1, b2, b3;
                asm volatile("ld.shared.v4.b32 {%0,%1,%2,%3}, [%4];"
                             : "=r"(b0), "=r"(b1), "=r"(b2), "=r"(b3)
                             : "r"(sbase + B0_OFF + (c * 4 + p) * 512 + lane * 16));
                mma16816(dm0[pp * 2],     a0, a1, a2, a3, b0, b1);
                mma16816(dm0[pp * 2 + 1], a0, a1, a2, a3, b2, b3);
            }
        }
        // ===== 6. wait B; reload h1new -> chunks 16-31; combine -> coords =====
        bt += 16; bar_wait(tile, bt);
        for (int u = t; u < 4096; u += NT) {
            int c = u >> 8, rem = u & 255, m = rem >> 1, hi = rem & 1;
            u32 dst = sbase + A_OFF + (16 + c) * 4096 + m * 32 + (((hi ^ (m >> 2)) & 1) << 4);
            CP16(dst, &g_h1p[(size_t)((tile * 16 + c) * 128 + m) * 16 + hi * 8]);
        }
        CP_COMMIT();
        // combine: warp w handles rows w*8..w*8+7, 2 rows per pass
#pragma unroll
        for (int ps = 0; ps < 4; ps++) {
            int row = w * 8 + 2 * ps + (lane >> 4);
            int qp = lane & 15;
            float4 P = __ldg(&g_part[(size_t)(tile * 128 + row) * 16 + qp]);
            float sh = P.x, sh2 = P.y, sA = P.z, sW = P.w;
#pragma unroll
            for (int off = 1; off < 4; off <<= 1) {
                sh  += __shfl_xor_sync(0xffffffffu, sh,  off);
                sh2 += __shfl_xor_sync(0xffffffffu, sh2, off);
                sA  += __shfl_xor_sync(0xffffffffu, sA,  off);
                sW  += __shfl_xor_sync(0xffffffffu, sW,  off);
            }
            float mu   = sh * (1.f / 64.f);
            float var  = sh2 * (1.f / 64.f) - mu * mu;
            float rstd = rsqrtf(var + EPSG);
            float vA = rstd * (sA - mu * gag);
            float vW = rstd * (sW - mu * gwg);
            if (lane & 3) { vA = 0.f; vW = 0.f; }
#pragma unroll
            for (int off = 4; off < 16; off <<= 1) {
                vA += __shfl_xor_sync(0xffffffffu, vA, off);
                vW += __shfl_xor_sync(0xffffffffu, vW, off);
            }
            if ((lane & 15) == 0) {
                float ang = tanh_fast(vA + BAt + bav);
                float wdt = sig_fast(vW + BWt + bwv);
                sc[row] = make_float2(ang, wdt);
                if (q == (row >> 3)) {
                    float2* op = (float2*)(out + ((size_t)(tile * 128 + row) * T + step) * 2);
                    *op = make_float2(ang, wdt);
                }
            }
        }
        CP_WAITALL();
        __syncthreads();
    }
}

extern "C" void kernel_launch(void* const* d_in, const int* in_sizes, int n_in,
                              void* d_out, int out_size) {
    const float* noise    = (const float*)d_in[0];
    const float* W_unpack = (const float*)d_in[1];
    const float* b_unpack = (const float*)d_in[2];
    const float* Wih0     = (const float*)d_in[3];
    const float* Whh0     = (const float*)d_in[4];
    const float* bih0     = (const float*)d_in[5];
    const float* bhh0     = (const float*)d_in[6];
    const float* Wih1     = (const float*)d_in[7];
    const float* Whh1     = (const float*)d_in[8];
    const float* bih1     = (const float*)d_in[9];
    const float* bhh1     = (const float*)d_in[10];
    const float* gamma_a  = (const float*)d_in[11];
    const float* beta_a   = (const float*)d_in[12];
    const float* Wa       = (const float*)d_in[13];
    const float* ba       = (const float*)d_in[14];
    const float* gamma_w  = (const float*)d_in[15];
    const float* beta_w   = (const float*)d_in[16];
    const float* Ww       = (const float*)d_in[17];
    const float* bw       = (const float*)d_in[18];
    (void)in_sizes; (void)n_in;

    int T = out_size / (BB * 2);

    cudaFuncSetAttribute(gen_kernel, cudaFuncAttributeMaxDynamicSharedMemorySize, SMEM_TOTAL);
    prep_kernel<<<512, 256>>>(W_unpack, Wih0, Whh0, bih0, bhh0, Wih1, Whh1, bih1, bhh1,
                              gamma_a, beta_a, Wa, gamma_w, beta_w, Ww);
    gen_kernel<<<NCTA, NT, SMEM_TOTAL>>>(noise, b_unpack, ba, bw, T, (float*)d_out);
}